// round 1
// baseline (speedup 1.0000x reference)
#include <cuda_runtime.h>
#include <math.h>

#define BATCH 4
#define C     64
#define H     160
#define W     160
#define HW    (H*W)
#define DG    4
#define KKTAP 9
#define CG    16
#define CO2   108    // 3*DG*KK
#define JDIM  576    // DG*CG*KK

// ---- scratch (no cudaMalloc allowed) ----
__device__ float g_off[BATCH * C   * HW];   // 26 MB  : 1x1 conv + BN output
__device__ float g_com[BATCH * CO2 * HW];   // 44 MB  : 3x3 conv output (raw)
__device__ float g_val[BATCH * JDIM * HW];  // 236 MB : sampled values * mask

// ============================================================
// K1: off_feat = BN(fea @ w_off)   (1x1 conv, per-pixel GEMV)
// ============================================================
__global__ __launch_bounds__(256) void k1_pointwise(
    const float* __restrict__ fea, const float* __restrict__ w_off,
    const float* __restrict__ gamma, const float* __restrict__ beta,
    const float* __restrict__ mean, const float* __restrict__ var)
{
    __shared__ float ws[64 * 64];   // transposed: ws[i][o]
    __shared__ float sc[64], sh[64];
    int t = threadIdx.x;
    for (int idx = t; idx < 4096; idx += 256) {
        int o = idx & 63, i = idx >> 6;
        ws[i * 64 + o] = w_off[o * 64 + i];
    }
    if (t < 64) {
        float inv = gamma[t] * rsqrtf(var[t] + 1e-5f);
        sc[t] = inv;
        sh[t] = beta[t] - mean[t] * inv;
    }
    __syncthreads();

    int b = blockIdx.y;
    int p = blockIdx.x * 256 + t;
    const float* fb = fea + (size_t)b * C * HW + p;

    float acc[64];
    #pragma unroll
    for (int o = 0; o < 64; o++) acc[o] = 0.f;

    #pragma unroll 4
    for (int i = 0; i < 64; i++) {
        float a = fb[(size_t)i * HW];
        const float4* w4 = (const float4*)(ws + i * 64);
        #pragma unroll
        for (int o4 = 0; o4 < 16; o4++) {
            float4 w = w4[o4];
            acc[4*o4+0] += a * w.x;
            acc[4*o4+1] += a * w.y;
            acc[4*o4+2] += a * w.z;
            acc[4*o4+3] += a * w.w;
        }
    }
    float* ob = g_off + (size_t)b * C * HW + p;
    #pragma unroll
    for (int o = 0; o < 64; o++)
        ob[(size_t)o * HW] = acc[o] * sc[o] + sh[o];
}

// ============================================================
// K2: com = conv3x3(off_feat, w_com) + b_com   (64 -> 108 ch)
// block: 256 thr = 32x8 spatial tile, 12 output channels
// ============================================================
#define TW  32
#define TH  8
#define OCT 12
#define ICT 8

__global__ __launch_bounds__(256) void k2_conv3x3(
    const float* __restrict__ w_com, const float* __restrict__ b_com)
{
    __shared__ float in_s[ICT][TH+2][TW+2];       // 8 * 10 * 34
    __shared__ float w_s[ICT * 9 * OCT];          // [(ic*9+tap)*12 + oc]
    int t   = threadIdx.x;
    int b   = blockIdx.z;
    int oc0 = blockIdx.y * OCT;
    int tile = blockIdx.x;                        // 0..99
    int ty0 = (tile / 5) * TH;
    int tx0 = (tile % 5) * TW;
    int tx = t & 31, ty = t >> 5;

    float acc[OCT];
    #pragma unroll
    for (int oc = 0; oc < OCT; oc++) acc[oc] = b_com[oc0 + oc];

    for (int ic0 = 0; ic0 < C; ic0 += ICT) {
        // load halo'd input tile
        for (int idx = t; idx < ICT * (TH+2) * (TW+2); idx += 256) {
            int ic = idx / ((TH+2)*(TW+2));
            int r  = idx % ((TH+2)*(TW+2));
            int yy = r / (TW+2), xx = r % (TW+2);
            int gy = ty0 + yy - 1, gx = tx0 + xx - 1;
            float v = 0.f;
            if (gy >= 0 && gy < H && gx >= 0 && gx < W)
                v = g_off[((size_t)(b * C + ic0 + ic)) * HW + gy * W + gx];
            in_s[ic][yy][xx] = v;
        }
        // load weights, oc-contiguous for float4 reads
        for (int idx = t; idx < ICT * 9 * OCT; idx += 256) {
            int oc  = idx % OCT;
            int rest = idx / OCT;
            int tap = rest % 9;
            int ic  = rest / 9;
            w_s[(ic * 9 + tap) * OCT + oc] =
                w_com[((size_t)(oc0 + oc) * C + ic0 + ic) * 9 + tap];
        }
        __syncthreads();

        #pragma unroll
        for (int ic = 0; ic < ICT; ic++) {
            float v[9];
            #pragma unroll
            for (int dy = 0; dy < 3; dy++)
                #pragma unroll
                for (int dx = 0; dx < 3; dx++)
                    v[dy*3+dx] = in_s[ic][ty+dy][tx+dx];
            #pragma unroll
            for (int tap = 0; tap < 9; tap++) {
                const float4* w4 = (const float4*)(w_s + (ic*9+tap) * OCT);
                float4 w0 = w4[0], w1 = w4[1], w2 = w4[2];
                float iv = v[tap];
                acc[0]  += iv*w0.x; acc[1]  += iv*w0.y; acc[2]  += iv*w0.z; acc[3]  += iv*w0.w;
                acc[4]  += iv*w1.x; acc[5]  += iv*w1.y; acc[6]  += iv*w1.z; acc[7]  += iv*w1.w;
                acc[8]  += iv*w2.x; acc[9]  += iv*w2.y; acc[10] += iv*w2.z; acc[11] += iv*w2.w;
            }
        }
        __syncthreads();
    }
    int p = (ty0 + ty) * W + tx0 + tx;
    #pragma unroll
    for (int oc = 0; oc < OCT; oc++)
        g_com[((size_t)(b * CO2 + oc0 + oc)) * HW + p] = acc[oc];
}

// ============================================================
// K3: bilinear sampling * sigmoid(mask) -> g_val[b][j][hw]
//     j = (g*CG + c)*KK + k   (matches w_dcn flat layout)
// ============================================================
__global__ __launch_bounds__(256) void k3_sample(const float* __restrict__ fea)
{
    int b = blockIdx.y;
    int p = blockIdx.x * 256 + threadIdx.x;
    int h = p / W, w = p % W;

    const float* comb = g_com + (size_t)b * CO2 * HW;
    const float* feab = fea + (size_t)b * C * HW;
    float* valb = g_val + (size_t)b * JDIM * HW;

    for (int g = 0; g < DG; g++) {
        #pragma unroll
        for (int k = 0; k < KKTAP; k++) {
            float dy = comb[(size_t)(g*18 + 2*k    ) * HW + p];
            float dx = comb[(size_t)(g*18 + 2*k + 1) * HW + p];
            float m  = comb[(size_t)(72 + g*9 + k  ) * HW + p];
            m = 1.f / (1.f + expf(-m));

            float py = dy + (float)(k / 3 - 1) + (float)h;
            float px = dx + (float)(k % 3 - 1) + (float)w;
            float y0f = floorf(py), x0f = floorf(px);
            float wy = py - y0f, wx = px - x0f;
            int y0 = (int)y0f, x0 = (int)x0f;
            int y1 = y0 + 1,   x1 = x0 + 1;

            bool vy0 = (y0 >= 0 && y0 < H), vy1 = (y1 >= 0 && y1 < H);
            bool vx0 = (x0 >= 0 && x0 < W), vx1 = (x1 >= 0 && x1 < W);
            float w00 = (1.f-wy)*(1.f-wx) * (float)(vy0 && vx0);
            float w01 = (1.f-wy)*wx       * (float)(vy0 && vx1);
            float w10 = wy*(1.f-wx)       * (float)(vy1 && vx0);
            float w11 = wy*wx             * (float)(vy1 && vx1);

            int y0c = min(max(y0, 0), H-1), y1c = min(max(y1, 0), H-1);
            int x0c = min(max(x0, 0), W-1), x1c = min(max(x1, 0), W-1);
            int i00 = y0c * W + x0c, i01 = y0c * W + x1c;
            int i10 = y1c * W + x0c, i11 = y1c * W + x1c;

            const float* fg = feab + (size_t)g * CG * HW;
            #pragma unroll
            for (int c = 0; c < CG; c++) {
                const float* fc = fg + (size_t)c * HW;
                float v = w00 * fc[i00] + w01 * fc[i01]
                        + w10 * fc[i10] + w11 * fc[i11];
                valb[((size_t)((g*CG + c) * KKTAP + k)) * HW + p] = v * m;
            }
        }
    }
}

// ============================================================
// K4: out = fea + relu(W_dcn[64,576] @ val[576,HW] + b_dcn)
// block: 64 oc x 64 px tile, 256 thr, 4x4 micro-tile
// ============================================================
__global__ __launch_bounds__(256) void k4_gemm(
    const float* __restrict__ w_dcn, const float* __restrict__ b_dcn,
    const float* __restrict__ fea, float* __restrict__ out)
{
    __shared__ float a_s[16][68];   // [kk][oc], padded
    __shared__ float b_s[16][64];   // [kk][px]
    int t  = threadIdx.x;
    int b  = blockIdx.z;
    int n0 = blockIdx.x * 64;
    int tm = (t >> 4) * 4;          // oc base 0..60
    int tn = (t & 15) * 4;          // px base 0..60

    float acc[4][4];
    #pragma unroll
    for (int i = 0; i < 4; i++)
        #pragma unroll
        for (int q = 0; q < 4; q++) acc[i][q] = 0.f;

    const float* vb = g_val + (size_t)b * JDIM * HW + n0;

    for (int j0 = 0; j0 < JDIM; j0 += 16) {
        // A: w_dcn[oc][j0+kk] -> a_s[kk][oc]  (coalesced over kk per oc)
        {
            int kk = t & 15;
            int oc = t >> 4;
            #pragma unroll
            for (int rep = 0; rep < 4; rep++)
                a_s[kk][oc + rep * 16] = w_dcn[(size_t)(oc + rep*16) * JDIM + j0 + kk];
        }
        // B: val[j0+kk][n0 + px]  (float4, coalesced)
        {
            int kk  = t >> 4;
            int pxq = (t & 15) * 4;
            float4 v = *(const float4*)(vb + (size_t)(j0 + kk) * HW + pxq);
            *(float4*)&b_s[kk][pxq] = v;
        }
        __syncthreads();
        #pragma unroll
        for (int kk = 0; kk < 16; kk++) {
            float4 a  = *(const float4*)&a_s[kk][tm];
            float4 bb = *(const float4*)&b_s[kk][tn];
            acc[0][0] += a.x*bb.x; acc[0][1] += a.x*bb.y; acc[0][2] += a.x*bb.z; acc[0][3] += a.x*bb.w;
            acc[1][0] += a.y*bb.x; acc[1][1] += a.y*bb.y; acc[1][2] += a.y*bb.z; acc[1][3] += a.y*bb.w;
            acc[2][0] += a.z*bb.x; acc[2][1] += a.z*bb.y; acc[2][2] += a.z*bb.z; acc[2][3] += a.z*bb.w;
            acc[3][0] += a.w*bb.x; acc[3][1] += a.w*bb.y; acc[3][2] += a.w*bb.z; acc[3][3] += a.w*bb.w;
        }
        __syncthreads();
    }

    #pragma unroll
    for (int i = 0; i < 4; i++) {
        int oc = tm + i;
        float bias = b_dcn[oc];
        size_t base = (size_t)(b * C + oc) * HW + n0 + tn;
        #pragma unroll
        for (int q = 0; q < 4; q++) {
            float r = fmaxf(acc[i][q] + bias, 0.f);
            out[base + q] = fea[base + q] + r;
        }
    }
}

// ============================================================
extern "C" void kernel_launch(void* const* d_in, const int* in_sizes, int n_in,
                              void* d_out, int out_size)
{
    const float* fea      = (const float*)d_in[0];
    const float* w_off    = (const float*)d_in[1];
    const float* bn_gamma = (const float*)d_in[2];
    const float* bn_beta  = (const float*)d_in[3];
    const float* bn_mean  = (const float*)d_in[4];
    const float* bn_var   = (const float*)d_in[5];
    const float* w_com    = (const float*)d_in[6];
    const float* b_com    = (const float*)d_in[7];
    const float* w_dcn    = (const float*)d_in[8];
    const float* b_dcn    = (const float*)d_in[9];
    float* out = (float*)d_out;

    k1_pointwise<<<dim3(HW/256, BATCH), 256>>>(fea, w_off, bn_gamma, bn_beta, bn_mean, bn_var);
    k2_conv3x3 <<<dim3(100, CO2/OCT, BATCH), 256>>>(w_com, b_com);
    k3_sample  <<<dim3(HW/256, BATCH), 256>>>(fea);
    k4_gemm    <<<dim3(HW/64, 1, BATCH), 256>>>(w_dcn, b_dcn, fea, out);
}

// round 2
// speedup vs baseline: 1.2008x; 1.2008x over previous
#include <cuda_runtime.h>
#include <math.h>

#define BATCH 4
#define C     64
#define H     160
#define W     160
#define HW    (H*W)
#define DG    4
#define KKTAP 9
#define CG    16
#define CO2   108    // 3*DG*KK
#define JDIM  576    // DG*CG*KK

// ---- scratch (no cudaMalloc allowed) ----
__device__ float g_off[BATCH * C   * HW];   // 26 MB : 1x1 conv + BN output
__device__ float g_com[BATCH * CO2 * HW];   // 44 MB : 3x3 conv output (raw)
__device__ float g_wt [JDIM * C];           // w_dcn transposed: [j][oc]

// ---------- packed f32x2 helpers (sm_100a FFMA2 path) ----------
__device__ __forceinline__ unsigned long long pack2(float lo, float hi) {
    unsigned long long r;
    asm("mov.b64 %0, {%1, %2};" : "=l"(r) : "f"(lo), "f"(hi));
    return r;
}
__device__ __forceinline__ void unpack2(unsigned long long v, float& lo, float& hi) {
    asm("mov.b64 {%0, %1}, %2;" : "=f"(lo), "=f"(hi) : "l"(v));
}
__device__ __forceinline__ void fma2(unsigned long long& d,
                                     unsigned long long a,
                                     unsigned long long b) {
    asm("fma.rn.f32x2 %0, %1, %2, %0;" : "+l"(d) : "l"(a), "l"(b));
}

// ============================================================
// K0: transpose w_dcn[oc][j] -> g_wt[j][oc]
// ============================================================
__global__ __launch_bounds__(256) void k0_transpose(const float* __restrict__ w_dcn)
{
    int idx = blockIdx.x * 256 + threadIdx.x;   // 0 .. 36863
    if (idx >= JDIM * C) return;
    int j  = idx >> 6;
    int oc = idx & 63;
    g_wt[idx] = w_dcn[(size_t)oc * JDIM + j];
}

// ============================================================
// K1: off_feat = BN(fea @ w_off)   (1x1 conv, per-pixel GEMV)
// ============================================================
__global__ __launch_bounds__(256) void k1_pointwise(
    const float* __restrict__ fea, const float* __restrict__ w_off,
    const float* __restrict__ gamma, const float* __restrict__ beta,
    const float* __restrict__ mean, const float* __restrict__ var)
{
    __shared__ float ws[64 * 64];   // transposed: ws[i][o]
    __shared__ float sc[64], sh[64];
    int t = threadIdx.x;
    for (int idx = t; idx < 4096; idx += 256) {
        int o = idx & 63, i = idx >> 6;
        ws[i * 64 + o] = w_off[o * 64 + i];
    }
    if (t < 64) {
        float inv = gamma[t] * rsqrtf(var[t] + 1e-5f);
        sc[t] = inv;
        sh[t] = beta[t] - mean[t] * inv;
    }
    __syncthreads();

    int b = blockIdx.y;
    int p = blockIdx.x * 256 + t;
    const float* fb = fea + (size_t)b * C * HW + p;

    unsigned long long acc[32];
    #pragma unroll
    for (int o = 0; o < 32; o++) acc[o] = 0ull;

    #pragma unroll 4
    for (int i = 0; i < 64; i++) {
        unsigned long long a2 = pack2(fb[(size_t)i * HW], fb[(size_t)i * HW]);
        const ulonglong2* w2 = (const ulonglong2*)(ws + i * 64);
        #pragma unroll
        for (int o4 = 0; o4 < 16; o4++) {
            ulonglong2 w = w2[o4];
            fma2(acc[2*o4+0], a2, w.x);
            fma2(acc[2*o4+1], a2, w.y);
        }
    }
    float* ob = g_off + (size_t)b * C * HW + p;
    #pragma unroll
    for (int o = 0; o < 32; o++) {
        float lo, hi;
        unpack2(acc[o], lo, hi);
        ob[(size_t)(2*o  ) * HW] = lo * sc[2*o  ] + sh[2*o  ];
        ob[(size_t)(2*o+1) * HW] = hi * sc[2*o+1] + sh[2*o+1];
    }
}

// ============================================================
// K2: com = conv3x3(off_feat, w_com) + b_com   (64 -> 108 ch)
// block: 256 thr = 32x8 layout, each thread does 2 pixels (y, y+8),
// 12 output channels, FFMA2 inner loop.
// ============================================================
#define TW  32
#define TH  16
#define OCT 12
#define ICT 8

__global__ __launch_bounds__(256) void k2_conv3x3(
    const float* __restrict__ w_com, const float* __restrict__ b_com)
{
    __shared__ float in_s[ICT][TH+2][TW+2];       // 8 * 18 * 34
    __shared__ float w_s[ICT * 9 * OCT];          // [(ic*9+tap)*12 + oc]
    int t   = threadIdx.x;
    int b   = blockIdx.z;
    int oc0 = blockIdx.y * OCT;
    int tile = blockIdx.x;                        // 0..49
    int ty0 = (tile / 5) * TH;
    int tx0 = (tile % 5) * TW;
    int tx = t & 31, ty = t >> 5;                 // ty 0..7

    unsigned long long acc[2][6];                 // [pixel][oc-pair]
    #pragma unroll
    for (int pxi = 0; pxi < 2; pxi++)
        #pragma unroll
        for (int j = 0; j < 6; j++) acc[pxi][j] = 0ull;

    for (int ic0 = 0; ic0 < C; ic0 += ICT) {
        // load halo'd input tile (8 ch x 18 x 34)
        for (int idx = t; idx < ICT * (TH+2) * (TW+2); idx += 256) {
            int ic = idx / ((TH+2)*(TW+2));
            int r  = idx % ((TH+2)*(TW+2));
            int yy = r / (TW+2), xx = r % (TW+2);
            int gy = ty0 + yy - 1, gx = tx0 + xx - 1;
            float v = 0.f;
            if (gy >= 0 && gy < H && gx >= 0 && gx < W)
                v = g_off[((size_t)(b * C + ic0 + ic)) * HW + gy * W + gx];
            in_s[ic][yy][xx] = v;
        }
        // load weights, oc-contiguous
        for (int idx = t; idx < ICT * 9 * OCT; idx += 256) {
            int oc  = idx % OCT;
            int rest = idx / OCT;
            int tap = rest % 9;
            int ic  = rest / 9;
            w_s[(ic * 9 + tap) * OCT + oc] =
                w_com[((size_t)(oc0 + oc) * C + ic0 + ic) * 9 + tap];
        }
        __syncthreads();

        #pragma unroll
        for (int ic = 0; ic < ICT; ic++) {
            float v0[9], v1[9];
            #pragma unroll
            for (int dy = 0; dy < 3; dy++)
                #pragma unroll
                for (int dx = 0; dx < 3; dx++) {
                    v0[dy*3+dx] = in_s[ic][ty     + dy][tx+dx];
                    v1[dy*3+dx] = in_s[ic][ty + 8 + dy][tx+dx];
                }
            #pragma unroll
            for (int tap = 0; tap < 9; tap++) {
                const ulonglong2* w2 = (const ulonglong2*)(w_s + (ic*9+tap) * OCT);
                ulonglong2 wA = w2[0];   // oc 0-3
                ulonglong2 wB = w2[1];   // oc 4-7
                ulonglong2 wC = w2[2];   // oc 8-11
                unsigned long long d0 = pack2(v0[tap], v0[tap]);
                unsigned long long d1 = pack2(v1[tap], v1[tap]);
                fma2(acc[0][0], d0, wA.x); fma2(acc[0][1], d0, wA.y);
                fma2(acc[0][2], d0, wB.x); fma2(acc[0][3], d0, wB.y);
                fma2(acc[0][4], d0, wC.x); fma2(acc[0][5], d0, wC.y);
                fma2(acc[1][0], d1, wA.x); fma2(acc[1][1], d1, wA.y);
                fma2(acc[1][2], d1, wB.x); fma2(acc[1][3], d1, wB.y);
                fma2(acc[1][4], d1, wC.x); fma2(acc[1][5], d1, wC.y);
            }
        }
        __syncthreads();
    }
    #pragma unroll
    for (int pxi = 0; pxi < 2; pxi++) {
        int p = (ty0 + ty + pxi * 8) * W + tx0 + tx;
        #pragma unroll
        for (int j = 0; j < 6; j++) {
            float lo, hi;
            unpack2(acc[pxi][j], lo, hi);
            g_com[((size_t)(b * CO2 + oc0 + 2*j    )) * HW + p] = lo + b_com[oc0 + 2*j];
            g_com[((size_t)(b * CO2 + oc0 + 2*j + 1)) * HW + p] = hi + b_com[oc0 + 2*j + 1];
        }
    }
}

// ============================================================
// K34: fused sampling + DCN GEMM + relu + residual.
// Block: 64 oc x 64 px, 256 threads. K loop over 36 chunks of 16
// (one (g,k) per chunk, 16 channels). Sampling params precomputed
// per block into smem; b_s tile produced on the fly from fea gathers.
// ============================================================
__global__ __launch_bounds__(256) void k34_fused(
    const float* __restrict__ fea, const float* __restrict__ b_dcn,
    float* __restrict__ out)
{
    __shared__ float s_py[36 * 64];
    __shared__ float s_px[36 * 64];
    __shared__ float s_m [36 * 64];
    __shared__ float a_s[16][64];   // [c][oc]
    __shared__ float b_s[16][64];   // [c][px]

    int t  = threadIdx.x;
    int b  = blockIdx.y;
    int n0 = blockIdx.x * 64;

    const float* comb = g_com + (size_t)b * CO2 * HW;
    const float* feab = fea + (size_t)b * C * HW;

    // ---- precompute sampling params: 36 (g,k) x 64 px ----
    for (int i = t; i < 36 * 64; i += 256) {
        int gk  = i >> 6;
        int pxi = i & 63;
        int g = gk / 9, k = gk - 9 * g;
        int p = n0 + pxi;
        int h = p / W, w = p - h * W;
        float dy = comb[(size_t)(g*18 + 2*k    ) * HW + p];
        float dx = comb[(size_t)(g*18 + 2*k + 1) * HW + p];
        float m  = comb[(size_t)(72 + g*9 + k  ) * HW + p];
        s_m [i] = 1.f / (1.f + expf(-m));
        s_py[i] = dy + (float)(k / 3 - 1) + (float)h;
        s_px[i] = dx + (float)(k % 3 - 1) + (float)w;
    }
    __syncthreads();

    // ---- accumulators: 4 oc x 4 px as 4x2 f32x2 pairs ----
    unsigned long long acc[4][2];
    #pragma unroll
    for (int i = 0; i < 4; i++) { acc[i][0] = 0ull; acc[i][1] = 0ull; }

    int tm = (t >> 4) * 4;          // oc base
    int tn = (t & 15) * 4;          // px base

    int pxi = t & 63;
    int c0  = (t >> 6) * 4;         // channel quad for b_s production

    for (int gk = 0; gk < 36; gk++) {
        int g = gk / 9, k = gk - 9 * g;

        // ---- produce b_s[c][px]: bilinear sample * mask ----
        {
            int i = gk * 64 + pxi;
            float py = s_py[i], px = s_px[i], m = s_m[i];
            float y0f = floorf(py), x0f = floorf(px);
            float wy = py - y0f, wx = px - x0f;
            int y0 = (int)y0f, x0 = (int)x0f;
            int y1 = y0 + 1,   x1 = x0 + 1;
            bool vy0 = (y0 >= 0 && y0 < H), vy1 = (y1 >= 0 && y1 < H);
            bool vx0 = (x0 >= 0 && x0 < W), vx1 = (x1 >= 0 && x1 < W);
            float w00 = (1.f-wy)*(1.f-wx) * (float)(vy0 && vx0) * m;
            float w01 = (1.f-wy)*wx       * (float)(vy0 && vx1) * m;
            float w10 = wy*(1.f-wx)       * (float)(vy1 && vx0) * m;
            float w11 = wy*wx             * (float)(vy1 && vx1) * m;
            int y0c = min(max(y0, 0), H-1), y1c = min(max(y1, 0), H-1);
            int x0c = min(max(x0, 0), W-1), x1c = min(max(x1, 0), W-1);
            int i00 = y0c * W + x0c, i01 = y0c * W + x1c;
            int i10 = y1c * W + x0c, i11 = y1c * W + x1c;

            const float* fg = feab + (size_t)(g * CG + c0) * HW;
            #pragma unroll
            for (int c = 0; c < 4; c++) {
                const float* fc = fg + (size_t)c * HW;
                b_s[c0 + c][pxi] = w00 * fc[i00] + w01 * fc[i01]
                                 + w10 * fc[i10] + w11 * fc[i11];
            }
        }
        // ---- load A chunk (coalesced from pre-transposed g_wt) ----
        #pragma unroll
        for (int r = 0; r < 4; r++) {
            int e  = t + r * 256;
            int c  = e >> 6;
            int oc = e & 63;
            a_s[c][oc] = g_wt[(size_t)((g * CG + c) * KKTAP + k) * 64 + oc];
        }
        __syncthreads();

        // ---- GEMM: 16-deep, 4x4 micro-tile, FFMA2 ----
        #pragma unroll
        for (int kk = 0; kk < 16; kk++) {
            float4 a = *(const float4*)&a_s[kk][tm];      // broadcast-ish
            ulonglong2 bb = *(const ulonglong2*)&b_s[kk][tn];
            unsigned long long a0 = pack2(a.x, a.x);
            unsigned long long a1 = pack2(a.y, a.y);
            unsigned long long a2 = pack2(a.z, a.z);
            unsigned long long a3 = pack2(a.w, a.w);
            fma2(acc[0][0], a0, bb.x); fma2(acc[0][1], a0, bb.y);
            fma2(acc[1][0], a1, bb.x); fma2(acc[1][1], a1, bb.y);
            fma2(acc[2][0], a2, bb.x); fma2(acc[2][1], a2, bb.y);
            fma2(acc[3][0], a3, bb.x); fma2(acc[3][1], a3, bb.y);
        }
        __syncthreads();
    }

    // ---- epilogue: bias, relu, residual ----
    #pragma unroll
    for (int i = 0; i < 4; i++) {
        int oc = tm + i;
        float bias = b_dcn[oc];
        size_t base = (size_t)(b * C + oc) * HW + n0 + tn;
        #pragma unroll
        for (int j = 0; j < 2; j++) {
            float lo, hi;
            unpack2(acc[i][j], lo, hi);
            out[base + 2*j    ] = fea[base + 2*j    ] + fmaxf(lo + bias, 0.f);
            out[base + 2*j + 1] = fea[base + 2*j + 1] + fmaxf(hi + bias, 0.f);
        }
    }
}

// ============================================================
extern "C" void kernel_launch(void* const* d_in, const int* in_sizes, int n_in,
                              void* d_out, int out_size)
{
    const float* fea      = (const float*)d_in[0];
    const float* w_off    = (const float*)d_in[1];
    const float* bn_gamma = (const float*)d_in[2];
    const float* bn_beta  = (const float*)d_in[3];
    const float* bn_mean  = (const float*)d_in[4];
    const float* bn_var   = (const float*)d_in[5];
    const float* w_com    = (const float*)d_in[6];
    const float* b_com    = (const float*)d_in[7];
    const float* w_dcn    = (const float*)d_in[8];
    const float* b_dcn    = (const float*)d_in[9];
    float* out = (float*)d_out;

    k0_transpose<<<(JDIM * C + 255) / 256, 256>>>(w_dcn);
    k1_pointwise<<<dim3(HW/256, BATCH), 256>>>(fea, w_off, bn_gamma, bn_beta, bn_mean, bn_var);
    k2_conv3x3 <<<dim3(50, CO2/OCT, BATCH), 256>>>(w_com, b_com);
    k34_fused  <<<dim3(HW/64, BATCH), 256>>>(fea, b_dcn, out);
}